// round 1
// baseline (speedup 1.0000x reference)
#include <cuda_runtime.h>
#include <cuda_bf16.h>
#include <stdint.h>

#define NN 4096
#define FIN 512
#define FOUT 128
#define HEADS 4
#define COUT 512              // HEADS*FOUT
#define ALPHA 0.2f
#define NEGV (-9000000000000000.0f)

// ---------------- scratch (no allocations allowed) ----------------
__device__ __align__(128) float g_H[NN * COUT];      // [n][h*128+o], 8 MB
__device__ __align__(128) float g_src[HEADS * NN];   // s_src + a_b
__device__ __align__(128) float g_dst[HEADS * NN];
__device__ __align__(128) float g_mx[HEADS * NN];
__device__ __align__(128) float g_inv[HEADS * NN];

// Fast exp on the FMA pipe (avoid MUFU.EX2 throughput wall).
// exp(x) = 2^(x*log2e); round-to-nearest int via magic constant; deg-5 poly on [-0.5,0.5].
__device__ __forceinline__ float fexp(float x) {
    float y = x * 1.4426950408889634f;
    y = fmaxf(y, -126.0f);
    float z = y + 12582912.0f;                 // 1.5*2^23
    int   k = __float_as_int(z) - 0x4B400000;
    float r = y - (z - 12582912.0f);           // exact
    float p = 1.3333558146428443e-3f;
    p = fmaf(p, r, 9.618129107628477e-3f);
    p = fmaf(p, r, 5.550410866482158e-2f);
    p = fmaf(p, r, 2.402265069591007e-1f);
    p = fmaf(p, r, 6.931471805599453e-1f);
    p = fmaf(p, r, 1.0f);
    return __int_as_float((k + 127) << 23) * p;
}

// ---------------- Kernel 1: g_H = x @ Wc + b  (4096x512x512) ----------------
// Wc(i, c) with c = h*128+o maps to W[h][i][o].
__global__ __launch_bounds__(256) void k_gemm_h(
    const float* __restrict__ x, const float* __restrict__ W, const float* __restrict__ b)
{
    __shared__ float As[16][68];   // [k][m], padded
    __shared__ float Bs[16][68];   // [k][c]
    const int t  = threadIdx.x;
    const int tx = t & 15, ty = t >> 4;
    const int c0 = blockIdx.x * 64;
    const int n0 = blockIdx.y * 64;
    const int h  = c0 >> 7;
    const int ob = c0 & 127;
    const float* Wh = W + h * FIN * FOUT;

    float acc[4][4];
#pragma unroll
    for (int i = 0; i < 4; i++)
#pragma unroll
        for (int j = 0; j < 4; j++) acc[i][j] = 0.f;

    const int arow = t >> 2, aks = (t & 3) * 4;    // A loader mapping
    const int bk = t >> 4, bcs = (t & 15) * 4;     // B loader mapping

    for (int k0 = 0; k0 < FIN; k0 += 16) {
        float4 av = *(const float4*)&x[(n0 + arow) * FIN + k0 + aks];
        As[aks + 0][arow] = av.x;
        As[aks + 1][arow] = av.y;
        As[aks + 2][arow] = av.z;
        As[aks + 3][arow] = av.w;
        float4 bv = *(const float4*)&Wh[(k0 + bk) * FOUT + ob + bcs];
        *(float4*)&Bs[bk][bcs] = bv;
        __syncthreads();
#pragma unroll
        for (int kk = 0; kk < 16; kk++) {
            float4 a4 = *(float4*)&As[kk][ty * 4];
            float4 b4 = *(float4*)&Bs[kk][tx * 4];
            float aa[4] = {a4.x, a4.y, a4.z, a4.w};
            float bb[4] = {b4.x, b4.y, b4.z, b4.w};
#pragma unroll
            for (int i = 0; i < 4; i++)
#pragma unroll
                for (int j = 0; j < 4; j++) acc[i][j] = fmaf(aa[i], bb[j], acc[i][j]);
        }
        __syncthreads();
    }
    float4 bias = *(const float4*)&b[c0 + tx * 4];
    float bb[4] = {bias.x, bias.y, bias.z, bias.w};
#pragma unroll
    for (int i = 0; i < 4; i++) {
        float4 v;
        v.x = acc[i][0] + bb[0]; v.y = acc[i][1] + bb[1];
        v.z = acc[i][2] + bb[2]; v.w = acc[i][3] + bb[3];
        *(float4*)&g_H[(n0 + ty * 4 + i) * COUT + c0 + tx * 4] = v;
    }
}

// ---------------- Kernel 2: s_src (+a_b), s_dst ----------------
__global__ __launch_bounds__(128) void k_scores(
    const float* __restrict__ aw, const float* __restrict__ ab)
{
    const int n = blockIdx.x;
    const int w = threadIdx.x >> 5;    // head
    const int l = threadIdx.x & 31;
    const float* hr = g_H + n * COUT + w * FOUT;
    float ss = 0.f, sd = 0.f;
#pragma unroll
    for (int j = 0; j < 4; j++) {
        int o = l + 32 * j;
        float v = hr[o];
        ss = fmaf(v, aw[w * 256 + o], ss);
        sd = fmaf(v, aw[w * 256 + 128 + o], sd);
    }
#pragma unroll
    for (int off = 16; off; off >>= 1) {
        ss += __shfl_xor_sync(0xffffffffu, ss, off);
        sd += __shfl_xor_sync(0xffffffffu, sd, off);
    }
    if (l == 0) {
        g_src[w * NN + n] = ss + ab[w];
        g_dst[w * NN + n] = sd;
    }
}

// ---------------- Kernel 3a: per-(head,row) softmax stats ----------------
__global__ __launch_bounds__(256) void k_stats(const int* __restrict__ adj)
{
    __shared__ float redm[8 * 4];
    __shared__ float MXs[4];
    __shared__ float SMs[4];
    const int n = blockIdx.x, t = threadIdx.x;
    const int lane = t & 31, warp = t >> 5;

    float sA[4];
#pragma unroll
    for (int h = 0; h < 4; h++) sA[h] = g_src[h * NN + n];

    const int* arow = adj + (size_t)n * NN;
    int acache[16];
    float mx[4] = {-3.0e38f, -3.0e38f, -3.0e38f, -3.0e38f};
#pragma unroll 4
    for (int r = 0; r < 16; r++) {
        int m = t + 256 * r;
        int a = arow[m];
        acache[r] = a;
#pragma unroll
        for (int h = 0; h < 4; h++) {
            float xx = sA[h] + g_dst[h * NN + m];
            float e = xx > 0.f ? xx : ALPHA * xx;
            e = (a > 0) ? e : NEGV;
            mx[h] = fmaxf(mx[h], e);
        }
    }
#pragma unroll
    for (int off = 16; off; off >>= 1)
#pragma unroll
        for (int h = 0; h < 4; h++) mx[h] = fmaxf(mx[h], __shfl_xor_sync(0xffffffffu, mx[h], off));
    if (lane == 0)
#pragma unroll
        for (int h = 0; h < 4; h++) redm[warp * 4 + h] = mx[h];
    __syncthreads();
    if (t < 4) {
        float v = redm[t];
#pragma unroll
        for (int w = 1; w < 8; w++) v = fmaxf(v, redm[w * 4 + t]);
        MXs[t] = v;
    }
    __syncthreads();
    float MXl[4] = {MXs[0], MXs[1], MXs[2], MXs[3]};
    float sm[4] = {0.f, 0.f, 0.f, 0.f};
#pragma unroll 4
    for (int r = 0; r < 16; r++) {
        int m = t + 256 * r;
        int a = acache[r];
#pragma unroll
        for (int h = 0; h < 4; h++) {
            float xx = sA[h] + g_dst[h * NN + m];
            float e = xx > 0.f ? xx : ALPHA * xx;
            e = (a > 0) ? e : NEGV;
            sm[h] += fexp(e - MXl[h]);
        }
    }
#pragma unroll
    for (int off = 16; off; off >>= 1)
#pragma unroll
        for (int h = 0; h < 4; h++) sm[h] += __shfl_xor_sync(0xffffffffu, sm[h], off);
    if (lane == 0)
#pragma unroll
        for (int h = 0; h < 4; h++) redm[warp * 4 + h] = sm[h];
    __syncthreads();
    if (t < 4) {
        float v = redm[t];
#pragma unroll
        for (int w = 1; w < 8; w++) v += redm[w * 4 + t];
        SMs[t] = v;
    }
    __syncthreads();
    if (t < 4) {
        g_mx[t * NN + n]  = MXs[t];
        g_inv[t * NN + n] = 1.0f / SMs[t];
    }
}

// ---------------- Kernel 3b: out = P @ H (P generated on the fly) ----------------
// Block = (head = blockIdx.x, 64-row n-tile = blockIdx.y). 128 threads, 8x8 micro-tiles.
__global__ __launch_bounds__(128) void k_attn(const int* __restrict__ adj, float* __restrict__ out)
{
    __shared__ float sdst[NN];          // full s_dst row for this head (16 KB)
    __shared__ float ssrc[64], smx[64], sinv[64];
    __shared__ float HsS[32 * 128];     // 16 KB
    __shared__ float PsS[32 * 64];      // 8 KB

    const int t  = threadIdx.x;
    const int h  = blockIdx.x;
    const int n0 = blockIdx.y * 64;

#pragma unroll
    for (int r = 0; r < 8; r++) {
        int idx = r * 512 + t * 4;
        *(float4*)&sdst[idx] = *(const float4*)&g_dst[h * NN + idx];
    }
    if (t < 64) {
        ssrc[t] = g_src[h * NN + n0 + t];
        smx[t]  = g_mx[h * NN + n0 + t];
        sinv[t] = g_inv[h * NN + n0 + t];
    }
    __syncthreads();

    const int np = t >> 1, seg = t & 1;          // P staging: thread -> (n, 16-m segment)
    const int cg = t & 15, ng = t >> 4;          // compute: 8x8 tile coords
    const float sS = ssrc[np], MX = smx[np], INV = sinv[np];
    const int* arowbase = adj + (size_t)(n0 + np) * NN + seg * 16;

    float acc[8][8];
#pragma unroll
    for (int i = 0; i < 8; i++)
#pragma unroll
        for (int j = 0; j < 8; j++) acc[i][j] = 0.f;

    for (int m0 = 0; m0 < NN; m0 += 32) {
        // ---- stage P[32m][64n] ----
        int4 a0 = *(const int4*)(arowbase + m0);
        int4 a1 = *(const int4*)(arowbase + m0 + 4);
        int4 a2 = *(const int4*)(arowbase + m0 + 8);
        int4 a3 = *(const int4*)(arowbase + m0 + 12);
        int aarr[16] = {a0.x, a0.y, a0.z, a0.w, a1.x, a1.y, a1.z, a1.w,
                        a2.x, a2.y, a2.z, a2.w, a3.x, a3.y, a3.z, a3.w};
#pragma unroll
        for (int j = 0; j < 16; j++) {
            int ml = seg * 16 + j;
            float xx = sS + sdst[m0 + ml];
            float e = xx > 0.f ? xx : ALPHA * xx;
            e = (aarr[j] > 0) ? e : NEGV;
            PsS[ml * 64 + np] = fexp(e - MX) * INV;
        }
        // ---- stage H[32m][128c] ----
#pragma unroll
        for (int r = 0; r < 8; r++) {
            int lin = r * 512 + t * 4;
            int mm = lin >> 7, c = lin & 127;
            *(float4*)&HsS[lin] = *(const float4*)&g_H[(m0 + mm) * COUT + h * FOUT + c];
        }
        __syncthreads();
        // ---- compute: acc[8n][8c] += P^T H ----
#pragma unroll 4
        for (int mm = 0; mm < 32; mm++) {
            float4 h0 = *(float4*)&HsS[mm * 128 + cg * 8];
            float4 h1 = *(float4*)&HsS[mm * 128 + cg * 8 + 4];
            float4 p0 = *(float4*)&PsS[mm * 64 + ng * 8];
            float4 p1 = *(float4*)&PsS[mm * 64 + ng * 8 + 4];
            float hv[8] = {h0.x, h0.y, h0.z, h0.w, h1.x, h1.y, h1.z, h1.w};
            float pv[8] = {p0.x, p0.y, p0.z, p0.w, p1.x, p1.y, p1.z, p1.w};
#pragma unroll
            for (int i = 0; i < 8; i++)
#pragma unroll
                for (int j = 0; j < 8; j++) acc[i][j] = fmaf(pv[i], hv[j], acc[i][j]);
        }
        __syncthreads();
    }

    // ---- epilogue: out[n][h*128 + c] ----
#pragma unroll
    for (int i = 0; i < 8; i++) {
        int n = n0 + ng * 8 + i;
#pragma unroll
        for (int j = 0; j < 8; j += 4) {
            float4 v;
            v.x = acc[i][j + 0]; v.y = acc[i][j + 1];
            v.z = acc[i][j + 2]; v.w = acc[i][j + 3];
            *(float4*)&out[(size_t)n * COUT + h * FOUT + cg * 8 + j] = v;
        }
    }
}

// ---------------- launch ----------------
extern "C" void kernel_launch(void* const* d_in, const int* in_sizes, int n_in,
                              void* d_out, int out_size)
{
    const float* x   = (const float*)d_in[0];
    const int*   adj = (const int*)d_in[1];
    const float* W   = (const float*)d_in[2];
    const float* b   = (const float*)d_in[3];
    const float* aw  = (const float*)d_in[4];
    const float* ab  = (const float*)d_in[5];
    float* out = (float*)d_out;

    k_gemm_h<<<dim3(COUT / 64, NN / 64), 256>>>(x, W, b);
    k_scores<<<NN, 128>>>(aw, ab);
    k_stats<<<NN, 256>>>(adj);
    k_attn<<<dim3(HEADS, NN / 64), 128>>>(adj, out);
}

// round 5
// speedup vs baseline: 1.5150x; 1.5150x over previous
#include <cuda_runtime.h>
#include <cuda_bf16.h>
#include <stdint.h>

#define NN 4096
#define FIN 512
#define FOUT 128
#define HEADS 4
#define COUT 512
#define ALPHA 0.2f

// ---------------- scratch ----------------
__device__ __align__(128) float g_H[NN * COUT];                 // [m][c_global] fp32, 8MB
__device__ __align__(128) float g_src[HEADS * NN];
__device__ __align__(128) float g_dst[HEADS * NN];
__device__ __align__(128) float g_inv[HEADS * NN];
__device__ __align__(128) __nv_bfloat16 g_Hthi[COUT * NN];      // [c_global][m] bf16 hi, 4MB
__device__ __align__(128) __nv_bfloat16 g_Htlo[COUT * NN];      // bf16 residual, 4MB

// ---------------- helpers ----------------
__device__ __forceinline__ uint32_t smem_u32(const void* p) {
    uint32_t a;
    asm("{ .reg .u64 t; cvta.to.shared.u64 t, %1; cvt.u32.u64 %0, t; }" : "=r"(a) : "l"(p));
    return a;
}
#define SWZ(off) ((off) ^ (((off) >> 3) & 0x70))

__device__ __forceinline__ void ldsm4(uint32_t* r, uint32_t a) {
    asm volatile("ldmatrix.sync.aligned.m8n8.x4.shared.b16 {%0,%1,%2,%3}, [%4];"
                 : "=r"(r[0]), "=r"(r[1]), "=r"(r[2]), "=r"(r[3]) : "r"(a));
}
__device__ __forceinline__ void mma16816(float* d, const uint32_t* a, const uint32_t* b) {
    asm volatile(
        "mma.sync.aligned.m16n8k16.row.col.f32.bf16.bf16.f32 "
        "{%0,%1,%2,%3},{%4,%5,%6,%7},{%8,%9},{%0,%1,%2,%3};"
        : "+f"(d[0]), "+f"(d[1]), "+f"(d[2]), "+f"(d[3])
        : "r"(a[0]), "r"(a[1]), "r"(a[2]), "r"(a[3]), "r"(b[0]), "r"(b[1]));
}

// ---------------- Kernel 1: g_H = x @ Wc + b ----------------
__global__ __launch_bounds__(256) void k_gemm_h(
    const float* __restrict__ x, const float* __restrict__ W, const float* __restrict__ b)
{
    __shared__ float As[16][68];
    __shared__ float Bs[16][68];
    const int t = threadIdx.x;
    const int tx = t & 15, ty = t >> 4;
    const int c0 = blockIdx.x * 64;
    const int n0 = blockIdx.y * 64;
    const int h = c0 >> 7, ob = c0 & 127;
    const float* Wh = W + h * FIN * FOUT;

    float acc[4][4];
#pragma unroll
    for (int i = 0; i < 4; i++)
#pragma unroll
        for (int j = 0; j < 4; j++) acc[i][j] = 0.f;

    const int arow = t >> 2, aks = (t & 3) * 4;
    const int bk = t >> 4, bcs = (t & 15) * 4;

    for (int k0 = 0; k0 < FIN; k0 += 16) {
        float4 av = *(const float4*)&x[(n0 + arow) * FIN + k0 + aks];
        As[aks + 0][arow] = av.x;
        As[aks + 1][arow] = av.y;
        As[aks + 2][arow] = av.z;
        As[aks + 3][arow] = av.w;
        *(float4*)&Bs[bk][bcs] = *(const float4*)&Wh[(k0 + bk) * FOUT + ob + bcs];
        __syncthreads();
#pragma unroll
        for (int kk = 0; kk < 16; kk++) {
            float4 a4 = *(float4*)&As[kk][ty * 4];
            float4 b4 = *(float4*)&Bs[kk][tx * 4];
            float aa[4] = {a4.x, a4.y, a4.z, a4.w};
            float bb[4] = {b4.x, b4.y, b4.z, b4.w};
#pragma unroll
            for (int i = 0; i < 4; i++)
#pragma unroll
                for (int j = 0; j < 4; j++) acc[i][j] = fmaf(aa[i], bb[j], acc[i][j]);
        }
        __syncthreads();
    }
    float4 bias = *(const float4*)&b[c0 + tx * 4];
    float bb[4] = {bias.x, bias.y, bias.z, bias.w};
#pragma unroll
    for (int i = 0; i < 4; i++) {
        float4 v;
        v.x = acc[i][0] + bb[0]; v.y = acc[i][1] + bb[1];
        v.z = acc[i][2] + bb[2]; v.w = acc[i][3] + bb[3];
        *(float4*)&g_H[(n0 + ty * 4 + i) * COUT + c0 + tx * 4] = v;
    }
}

// ---------------- Kernel 2: scores ----------------
__global__ __launch_bounds__(128) void k_scores(
    const float* __restrict__ aw, const float* __restrict__ ab)
{
    const int n = blockIdx.x;
    const int w = threadIdx.x >> 5, l = threadIdx.x & 31;
    const float* hr = g_H + n * COUT + w * FOUT;
    float ss = 0.f, sd = 0.f;
#pragma unroll
    for (int j = 0; j < 4; j++) {
        int o = l + 32 * j;
        float v = hr[o];
        ss = fmaf(v, aw[w * 256 + o], ss);
        sd = fmaf(v, aw[w * 256 + 128 + o], sd);
    }
#pragma unroll
    for (int off = 16; off; off >>= 1) {
        ss += __shfl_xor_sync(0xffffffffu, ss, off);
        sd += __shfl_xor_sync(0xffffffffu, sd, off);
    }
    if (l == 0) {
        g_src[w * NN + n] = ss + ab[w];
        g_dst[w * NN + n] = sd;
    }
}

// ---------------- Kernel 3: softmax denominators (single pass, scores bounded) ----------------
__global__ __launch_bounds__(256) void k_stats(const int* __restrict__ adj)
{
    __shared__ float red[8 * 4];
    const int n = blockIdx.x, t = threadIdx.x;
    const int lane = t & 31, warp = t >> 5;

    float sA[4];
#pragma unroll
    for (int h = 0; h < 4; h++) sA[h] = g_src[h * NN + n];

    const int* arow = adj + (size_t)n * NN;
    float sm[4] = {0.f, 0.f, 0.f, 0.f};
#pragma unroll 4
    for (int r = 0; r < 16; r++) {
        int m = t + 256 * r;
        int a = arow[m];
        if (a > 0) {
#pragma unroll
            for (int h = 0; h < 4; h++) {
                float xx = sA[h] + g_dst[h * NN + m];
                float e = xx > 0.f ? xx : ALPHA * xx;
                sm[h] += __expf(e);
            }
        }
    }
#pragma unroll
    for (int off = 16; off; off >>= 1)
#pragma unroll
        for (int h = 0; h < 4; h++) sm[h] += __shfl_xor_sync(0xffffffffu, sm[h], off);
    if (lane == 0)
#pragma unroll
        for (int h = 0; h < 4; h++) red[warp * 4 + h] = sm[h];
    __syncthreads();
    if (t < 4) {
        float v = red[t];
#pragma unroll
        for (int w = 1; w < 8; w++) v += red[w * 4 + t];
        g_inv[t * NN + n] = 1.0f / v;
    }
}

// ---------------- Kernel 4: transpose + bf16 hi/lo split of H ----------------
__global__ __launch_bounds__(256) void k_cvt()
{
    __shared__ float tile[32][33];
    const int tx = threadIdx.x & 31, ty = threadIdx.x >> 5;
    const int m0 = blockIdx.x * 32, c0 = blockIdx.y * 32;
#pragma unroll
    for (int k = 0; k < 4; k++)
        tile[ty + 8 * k][tx] = g_H[(size_t)(m0 + ty + 8 * k) * COUT + c0 + tx];
    __syncthreads();
#pragma unroll
    for (int k = 0; k < 4; k++) {
        int cg = c0 + ty + 8 * k;
        float v = tile[tx][ty + 8 * k];
        __nv_bfloat16 hi = __float2bfloat16(v);
        __nv_bfloat16 lo = __float2bfloat16(v - __bfloat162float(hi));
        g_Hthi[(size_t)cg * NN + m0 + tx] = hi;
        g_Htlo[(size_t)cg * NN + m0 + tx] = lo;
    }
}

// ---------------- Kernel 5: out = P @ H via HMMA (bf16 hi/lo, 3 terms) ----------------
// smem layout (dynamic):
//   0:       sdst[4096] f32 (16KB)
//   16384:   ssrc[128]  (512B)
//   16896:   sinv[128]  (512B)
//   17408:   8 tiles of 16KB: Ah0 Ah1 Al0 Al1 Bh0 Bh1 Bl0 Bl1
#define SM_SDST 0
#define SM_SSRC 16384
#define SM_SINV 16896
#define SM_TILES 17408
#define TILE_B 16384
#define SMEM_TOTAL (SM_TILES + 8 * TILE_B)

__global__ __launch_bounds__(256) void k_attn_mma(const int* __restrict__ adj, float* __restrict__ out)
{
    extern __shared__ char smem[];
    const uint32_t sb = smem_u32(smem);
    const int t = threadIdx.x;
    const int wid = t >> 5, l = t & 31;
    const int h = blockIdx.x & 3;
    const int n0 = (blockIdx.x >> 2) * 128;

    // ---- stage per-block softmax data ----
    {
        float4* d = (float4*)(smem + SM_SDST);
        const float4* s = (const float4*)(g_dst + h * NN);
#pragma unroll
        for (int r = 0; r < 4; r++) d[t + 256 * r] = s[t + 256 * r];
    }
    if (t < 128) {
        ((float*)(smem + SM_SSRC))[t] = g_src[h * NN + n0 + t];
        ((float*)(smem + SM_SINV))[t] = g_inv[h * NN + n0 + t];
    }
    __syncthreads();

    // ---- staging role: thread -> (row np 0..127, 32-m half) ----
    const int np = t >> 1, mseg = (t & 1) * 32;
    const float sS  = ((const float*)(smem + SM_SSRC))[np];
    const float INV = ((const float*)(smem + SM_SINV))[np];
    const float* sdst = (const float*)(smem + SM_SDST);
    const int* arow = adj + (size_t)(n0 + np) * NN + mseg;
    const __nv_bfloat16* ghi = g_Hthi + (size_t)(h * 128 + np) * NN + mseg;
    const __nv_bfloat16* glo = g_Htlo + (size_t)(h * 128 + np) * NN + mseg;

    // ---- compute role: warp (wr, wc) owns 32m x 64n output tile ----
    const int wr = wid & 3;      // output-row group (P rows)
    const int wc = wid >> 2;     // output-col group (H cols)
    const uint32_t aBase0 = (uint32_t)((wr * 32 + (l & 15)) * 128 + ((l >> 4) << 4));
    const uint32_t aBase1 = aBase0 + 16 * 128;
    uint32_t bBase[4];
#pragma unroll
    for (int gg = 0; gg < 4; gg++)
        bBase[gg] = (uint32_t)((wc * 64 + gg * 16 + (l & 15)) * 128 + ((l >> 4) << 4));

    float acc[2][8][4];
#pragma unroll
    for (int mt = 0; mt < 2; mt++)
#pragma unroll
        for (int nt = 0; nt < 8; nt++)
#pragma unroll
            for (int q = 0; q < 4; q++) acc[mt][nt][q] = 0.f;

    auto stage = [&](int chunk) {
        const int m0 = chunk * 64;
        const int buf = chunk & 1;
        char* Ah = smem + SM_TILES + buf * TILE_B;
        char* Al = smem + SM_TILES + (2 + buf) * TILE_B;
        char* Bh = smem + SM_TILES + (4 + buf) * TILE_B;
        char* Bl = smem + SM_TILES + (6 + buf) * TILE_B;
        uint4 vh[4], vl[4];
#pragma unroll
        for (int g = 0; g < 4; g++) {
            vh[g] = *(const uint4*)(ghi + m0 + g * 8);
            vl[g] = *(const uint4*)(glo + m0 + g * 8);
        }
        int av[32];
#pragma unroll
        for (int g2 = 0; g2 < 8; g2++)
            *(int4*)(av + g2 * 4) = *(const int4*)(arow + m0 + g2 * 4);
#pragma unroll
        for (int g = 0; g < 4; g++) {
            __align__(16) __nv_bfloat16 hb[8];
            __align__(16) __nv_bfloat16 lb[8];
#pragma unroll
            for (int j = 0; j < 8; j++) {
                float xx = sS + sdst[m0 + mseg + g * 8 + j];
                float e = xx > 0.f ? xx : ALPHA * xx;
                float p = (av[g * 8 + j] > 0) ? __expf(e) * INV : 0.f;
                __nv_bfloat16 hi = __float2bfloat16(p);
                hb[j] = hi;
                lb[j] = __float2bfloat16(p - __bfloat162float(hi));
            }
            uint32_t sw = SWZ((uint32_t)(np * 128 + mseg * 2 + g * 16));
            *(uint4*)(Ah + sw) = *(const uint4*)hb;
            *(uint4*)(Al + sw) = *(const uint4*)lb;
            *(uint4*)(Bh + sw) = vh[g];
            *(uint4*)(Bl + sw) = vl[g];
        }
    };

    auto compute = [&](int buf) {
        const uint32_t tAh = sb + SM_TILES + buf * TILE_B;
        const uint32_t tAl = sb + SM_TILES + (2 + buf) * TILE_B;
        const uint32_t tBh = sb + SM_TILES + (4 + buf) * TILE_B;
        const uint32_t tBl = sb + SM_TILES + (6 + buf) * TILE_B;
#pragma unroll
        for (int ks = 0; ks < 4; ks++) {
            uint32_t ah[2][4], al[2][4], bh[4][4], bl[4][4];
            ldsm4(ah[0], tAh + SWZ(aBase0 + ks * 32));
            ldsm4(ah[1], tAh + SWZ(aBase1 + ks * 32));
            ldsm4(al[0], tAl + SWZ(aBase0 + ks * 32));
            ldsm4(al[1], tAl + SWZ(aBase1 + ks * 32));
#pragma unroll
            for (int gg = 0; gg < 4; gg++) {
                ldsm4(bh[gg], tBh + SWZ(bBase[gg] + ks * 32));
                ldsm4(bl[gg], tBl + SWZ(bBase[gg] + ks * 32));
            }
#pragma unroll
            for (int mt = 0; mt < 2; mt++)
#pragma unroll
                for (int nt = 0; nt < 8; nt++) {
                    uint32_t bfh[2] = {bh[nt >> 1][nt & 1], bh[nt >> 1][(nt & 1) + 2]};
                    uint32_t bfl[2] = {bl[nt >> 1][nt & 1], bl[nt >> 1][(nt & 1) + 2]};
                    mma16816(acc[mt][nt], ah[mt], bfh);
                    mma16816(acc[mt][nt], al[mt], bfh);
                    mma16816(acc[mt][nt], ah[mt], bfl);
                }
        }
    };

    stage(0);
    __syncthreads();
    for (int chunk = 0; chunk < 64; chunk++) {
        if (chunk + 1 < 64) stage(chunk + 1);
        compute(chunk & 1);
        __syncthreads();
    }

    // ---- epilogue ----
    const int rq = l >> 2, cq = (l & 3) * 2;
#pragma unroll
    for (int mt = 0; mt < 2; mt++) {
#pragma unroll
        for (int nt = 0; nt < 8; nt++) {
            int n = n0 + wr * 32 + mt * 16 + rq;
            int cg = h * FOUT + wc * 64 + nt * 8 + cq;
            float2 v0 = {acc[mt][nt][0], acc[mt][nt][1]};
            float2 v1 = {acc[mt][nt][2], acc[mt][nt][3]};
            *(float2*)&out[(size_t)n * COUT + cg] = v0;
            *(float2*)&out[(size_t)(n + 8) * COUT + cg] = v1;
        }
    }
}

// ---------------- launch ----------------
extern "C" void kernel_launch(void* const* d_in, const int* in_sizes, int n_in,
                              void* d_out, int out_size)
{
    const float* x   = (const float*)d_in[0];
    const int*   adj = (const int*)d_in[1];
    const float* W   = (const float*)d_in[2];
    const float* b   = (const float*)d_in[3];
    const float* aw  = (const float*)d_in[4];
    const float* ab  = (const float*)d_in[5];
    float* out = (float*)d_out;

    (void)cudaFuncSetAttribute(k_attn_mma, cudaFuncAttributeMaxDynamicSharedMemorySize, SMEM_TOTAL);

    k_gemm_h<<<dim3(COUT / 64, NN / 64), 256>>>(x, W, b);
    k_scores<<<NN, 128>>>(aw, ab);
    k_stats<<<NN, 256>>>(adj);
    k_cvt<<<dim3(NN / 32, COUT / 32), 256>>>();
    k_attn_mma<<<128, 256, SMEM_TOTAL>>>(adj, out);
}

// round 6
// speedup vs baseline: 2.1012x; 1.3869x over previous
#include <cuda_runtime.h>
#include <cuda_bf16.h>
#include <stdint.h>

#define NN 4096
#define FIN 512
#define FOUT 128
#define HEADS 4
#define COUT 512
#define ALPHA 0.2f

// ---------------- scratch ----------------
__device__ __align__(128) float g_H[NN * COUT];                 // [m][c_global] fp32, 8MB
__device__ __align__(128) float g_src[HEADS * NN];
__device__ __align__(128) float g_dst[HEADS * NN];
__device__ __align__(128) float g_inv[HEADS * NN];
__device__ __align__(128) __nv_bfloat16 g_Hthi[COUT * NN];      // [c_global][m] bf16 hi, 4MB
__device__ __align__(128) __nv_bfloat16 g_Htlo[COUT * NN];      // bf16 residual, 4MB

// ---------------- helpers ----------------
__device__ __forceinline__ uint32_t smem_u32(const void* p) {
    uint32_t a;
    asm("{ .reg .u64 t; cvta.to.shared.u64 t, %1; cvt.u32.u64 %0, t; }" : "=r"(a) : "l"(p));
    return a;
}
#define SWZ(off) ((off) ^ (((off) >> 3) & 0x70))

__device__ __forceinline__ void ldsm4(uint32_t* r, uint32_t a) {
    asm volatile("ldmatrix.sync.aligned.m8n8.x4.shared.b16 {%0,%1,%2,%3}, [%4];"
                 : "=r"(r[0]), "=r"(r[1]), "=r"(r[2]), "=r"(r[3]) : "r"(a));
}
__device__ __forceinline__ void mma16816(float* d, const uint32_t* a, const uint32_t* b) {
    asm volatile(
        "mma.sync.aligned.m16n8k16.row.col.f32.bf16.bf16.f32 "
        "{%0,%1,%2,%3},{%4,%5,%6,%7},{%8,%9},{%0,%1,%2,%3};"
        : "+f"(d[0]), "+f"(d[1]), "+f"(d[2]), "+f"(d[3])
        : "r"(a[0]), "r"(a[1]), "r"(a[2]), "r"(a[3]), "r"(b[0]), "r"(b[1]));
}

// ---------------- Kernel 1: g_H = x @ Wc + b ----------------
__global__ __launch_bounds__(256) void k_gemm_h(
    const float* __restrict__ x, const float* __restrict__ W, const float* __restrict__ b)
{
    __shared__ float As[16][68];
    __shared__ float Bs[16][68];
    const int t = threadIdx.x;
    const int tx = t & 15, ty = t >> 4;
    const int c0 = blockIdx.x * 64;
    const int n0 = blockIdx.y * 64;
    const int h = c0 >> 7, ob = c0 & 127;
    const float* Wh = W + h * FIN * FOUT;

    float acc[4][4];
#pragma unroll
    for (int i = 0; i < 4; i++)
#pragma unroll
        for (int j = 0; j < 4; j++) acc[i][j] = 0.f;

    const int arow = t >> 2, aks = (t & 3) * 4;
    const int bk = t >> 4, bcs = (t & 15) * 4;

    for (int k0 = 0; k0 < FIN; k0 += 16) {
        float4 av = *(const float4*)&x[(n0 + arow) * FIN + k0 + aks];
        As[aks + 0][arow] = av.x;
        As[aks + 1][arow] = av.y;
        As[aks + 2][arow] = av.z;
        As[aks + 3][arow] = av.w;
        *(float4*)&Bs[bk][bcs] = *(const float4*)&Wh[(k0 + bk) * FOUT + ob + bcs];
        __syncthreads();
#pragma unroll
        for (int kk = 0; kk < 16; kk++) {
            float4 a4 = *(float4*)&As[kk][ty * 4];
            float4 b4 = *(float4*)&Bs[kk][tx * 4];
            float aa[4] = {a4.x, a4.y, a4.z, a4.w};
            float bb[4] = {b4.x, b4.y, b4.z, b4.w};
#pragma unroll
            for (int i = 0; i < 4; i++)
#pragma unroll
                for (int j = 0; j < 4; j++) acc[i][j] = fmaf(aa[i], bb[j], acc[i][j]);
        }
        __syncthreads();
    }
    float4 bias = *(const float4*)&b[c0 + tx * 4];
    float bb[4] = {bias.x, bias.y, bias.z, bias.w};
#pragma unroll
    for (int i = 0; i < 4; i++) {
        float4 v;
        v.x = acc[i][0] + bb[0]; v.y = acc[i][1] + bb[1];
        v.z = acc[i][2] + bb[2]; v.w = acc[i][3] + bb[3];
        *(float4*)&g_H[(n0 + ty * 4 + i) * COUT + c0 + tx * 4] = v;
    }
}

// ---------------- Kernel 2: scores ----------------
__global__ __launch_bounds__(128) void k_scores(
    const float* __restrict__ aw, const float* __restrict__ ab)
{
    const int n = blockIdx.x;
    const int w = threadIdx.x >> 5, l = threadIdx.x & 31;
    const float* hr = g_H + n * COUT + w * FOUT;
    float ss = 0.f, sd = 0.f;
#pragma unroll
    for (int j = 0; j < 4; j++) {
        int o = l + 32 * j;
        float v = hr[o];
        ss = fmaf(v, aw[w * 256 + o], ss);
        sd = fmaf(v, aw[w * 256 + 128 + o], sd);
    }
#pragma unroll
    for (int off = 16; off; off >>= 1) {
        ss += __shfl_xor_sync(0xffffffffu, ss, off);
        sd += __shfl_xor_sync(0xffffffffu, sd, off);
    }
    if (l == 0) {
        g_src[w * NN + n] = ss + ab[w];
        g_dst[w * NN + n] = sd;
    }
}

// ---------------- Kernel 3: softmax denominators (single pass, scores bounded) ----------------
__global__ __launch_bounds__(256) void k_stats(const int* __restrict__ adj)
{
    __shared__ float red[8 * 4];
    const int n = blockIdx.x, t = threadIdx.x;
    const int lane = t & 31, warp = t >> 5;

    float sA[4];
#pragma unroll
    for (int h = 0; h < 4; h++) sA[h] = g_src[h * NN + n];

    const int* arow = adj + (size_t)n * NN;
    float sm[4] = {0.f, 0.f, 0.f, 0.f};
#pragma unroll 4
    for (int r = 0; r < 16; r++) {
        int m = t + 256 * r;
        int a = arow[m];
        if (a > 0) {
#pragma unroll
            for (int h = 0; h < 4; h++) {
                float xx = sA[h] + g_dst[h * NN + m];
                float e = xx > 0.f ? xx : ALPHA * xx;
                sm[h] += __expf(e);
            }
        }
    }
#pragma unroll
    for (int off = 16; off; off >>= 1)
#pragma unroll
        for (int h = 0; h < 4; h++) sm[h] += __shfl_xor_sync(0xffffffffu, sm[h], off);
    if (lane == 0)
#pragma unroll
        for (int h = 0; h < 4; h++) red[warp * 4 + h] = sm[h];
    __syncthreads();
    if (t < 4) {
        float v = red[t];
#pragma unroll
        for (int w = 1; w < 8; w++) v += red[w * 4 + t];
        g_inv[t * NN + n] = 1.0f / v;
    }
}

// ---------------- Kernel 4: transpose + bf16 hi/lo split of H ----------------
__global__ __launch_bounds__(256) void k_cvt()
{
    __shared__ float tile[32][33];
    const int tx = threadIdx.x & 31, ty = threadIdx.x >> 5;
    const int m0 = blockIdx.x * 32, c0 = blockIdx.y * 32;
#pragma unroll
    for (int k = 0; k < 4; k++)
        tile[ty + 8 * k][tx] = g_H[(size_t)(m0 + ty + 8 * k) * COUT + c0 + tx];
    __syncthreads();
#pragma unroll
    for (int k = 0; k < 4; k++) {
        int cg = c0 + ty + 8 * k;
        float v = tile[tx][ty + 8 * k];
        __nv_bfloat16 hi = __float2bfloat16(v);
        __nv_bfloat16 lo = __float2bfloat16(v - __bfloat162float(hi));
        g_Hthi[(size_t)cg * NN + m0 + tx] = hi;
        g_Htlo[(size_t)cg * NN + m0 + tx] = lo;
    }
}

// ---------------- Kernel 5: out = P @ H via HMMA, 64n x 128c per CTA ----------------
// smem: Ah[2]@0 (8KB ea), Al[2]@16K, Bh[2]@32K (16KB ea), Bl[2]@64K ; total 96KB
#define TILE_PA 8192
#define TILE_HB 16384
#define SM_AH(buf) ((buf) * TILE_PA)
#define SM_AL(buf) (16384 + (buf) * TILE_PA)
#define SM_BH(buf) (32768 + (buf) * TILE_HB)
#define SM_BL(buf) (65536 + (buf) * TILE_HB)
#define SMEM_TOTAL 98304

__global__ __launch_bounds__(256, 2) void k_attn_mma(const int* __restrict__ adj, float* __restrict__ out)
{
    extern __shared__ char smem[];
    const uint32_t sb = smem_u32(smem);
    const int t = threadIdx.x;
    const int wid = t >> 5, l = t & 31;
    const int h = blockIdx.x & 3;
    const int n0 = (blockIdx.x >> 2) * 64;

    // ---- staging roles ----
    const int np = t >> 2, mg = (t & 3) * 16;     // P: row np (0..63), m-offset mg
    const int cr = t >> 1, mh = (t & 1) * 32;     // H: row cr (0..127), m-offset mh
    const float sS  = g_src[h * NN + n0 + np];
    const float INV = g_inv[h * NN + n0 + np];
    const int* arow = adj + (size_t)(n0 + np) * NN + mg;
    const float* gdst = g_dst + h * NN + mg;
    const __nv_bfloat16* ghi = g_Hthi + (size_t)(h * 128 + cr) * NN + mh;
    const __nv_bfloat16* glo = g_Htlo + (size_t)(h * 128 + cr) * NN + mh;

    // ---- compute role: warp (wr, wc) owns 16n x 64c ----
    const int wr = wid & 3;
    const int wc = wid >> 2;
    const uint32_t aBase = (uint32_t)((wr * 16 + (l & 15)) * 128 + ((l >> 4) << 4));
    uint32_t bBase[4];
#pragma unroll
    for (int gg = 0; gg < 4; gg++)
        bBase[gg] = (uint32_t)((wc * 64 + gg * 16 + (l & 15)) * 128 + ((l >> 4) << 4));

    float acc[8][4];
#pragma unroll
    for (int nt = 0; nt < 8; nt++)
#pragma unroll
        for (int q = 0; q < 4; q++) acc[nt][q] = 0.f;

    auto stage = [&](int chunk) {
        const int m0 = chunk * 64;
        const int buf = chunk & 1;
        // ---- H tile: row cr, 32 m's (64B hi + 64B lo) ----
        {
            char* Bh = smem + SM_BH(buf);
            char* Bl = smem + SM_BL(buf);
            const uint32_t base = (uint32_t)(cr * 128 + mh * 2);
#pragma unroll
            for (int q = 0; q < 4; q++) {
                uint4 vh = *(const uint4*)(ghi + m0 + q * 8);
                *(uint4*)(Bh + SWZ(base + q * 16)) = vh;
            }
#pragma unroll
            for (int q = 0; q < 4; q++) {
                uint4 vl = *(const uint4*)(glo + m0 + q * 8);
                *(uint4*)(Bl + SWZ(base + q * 16)) = vl;
            }
        }
        // ---- P tile: row np, 16 m's ----
        {
            char* Ah = smem + SM_AH(buf);
            char* Al = smem + SM_AL(buf);
            const uint32_t base = (uint32_t)(np * 128 + mg * 2);
#pragma unroll
            for (int half = 0; half < 2; half++) {
                int4 a0 = *(const int4*)(arow + m0 + half * 8);
                int4 a1 = *(const int4*)(arow + m0 + half * 8 + 4);
                float4 d0 = *(const float4*)(gdst + m0 + half * 8);
                float4 d1 = *(const float4*)(gdst + m0 + half * 8 + 4);
                int av[8] = {a0.x, a0.y, a0.z, a0.w, a1.x, a1.y, a1.z, a1.w};
                float dv[8] = {d0.x, d0.y, d0.z, d0.w, d1.x, d1.y, d1.z, d1.w};
                __align__(16) __nv_bfloat16 hb[8];
                __align__(16) __nv_bfloat16 lb[8];
#pragma unroll
                for (int j = 0; j < 8; j++) {
                    float xx = sS + dv[j];
                    float e = xx > 0.f ? xx : ALPHA * xx;
                    float p = (av[j] > 0) ? __expf(e) * INV : 0.f;
                    __nv_bfloat16 hi = __float2bfloat16(p);
                    hb[j] = hi;
                    lb[j] = __float2bfloat16(p - __bfloat162float(hi));
                }
                uint32_t sw = SWZ(base + half * 16);
                *(uint4*)(Ah + sw) = *(const uint4*)hb;
                *(uint4*)(Al + sw) = *(const uint4*)lb;
            }
        }
    };

    auto compute = [&](int buf) {
        const uint32_t tAh = sb + SM_AH(buf);
        const uint32_t tAl = sb + SM_AL(buf);
        const uint32_t tBh = sb + SM_BH(buf);
        const uint32_t tBl = sb + SM_BL(buf);
#pragma unroll
        for (int ks = 0; ks < 4; ks++) {
            uint32_t ah[4], al[4], bh[4][4], bl[4][4];
            ldsm4(ah, tAh + SWZ(aBase + ks * 32));
            ldsm4(al, tAl + SWZ(aBase + ks * 32));
#pragma unroll
            for (int gg = 0; gg < 4; gg++) {
                ldsm4(bh[gg], tBh + SWZ(bBase[gg] + ks * 32));
                ldsm4(bl[gg], tBl + SWZ(bBase[gg] + ks * 32));
            }
#pragma unroll
            for (int nt = 0; nt < 8; nt++) {
                uint32_t bfh[2] = {bh[nt >> 1][nt & 1], bh[nt >> 1][(nt & 1) + 2]};
                uint32_t bfl[2] = {bl[nt >> 1][nt & 1], bl[nt >> 1][(nt & 1) + 2]};
                mma16816(acc[nt], ah, bfh);
                mma16816(acc[nt], al, bfh);
                mma16816(acc[nt], ah, bfl);
            }
        }
    };

    stage(0);
    __syncthreads();
    for (int chunk = 0; chunk < 64; chunk++) {
        if (chunk + 1 < 64) stage(chunk + 1);
        compute(chunk & 1);
        __syncthreads();
    }

    // ---- epilogue: warp writes 16n x 64c ----
    const int rq = l >> 2, cq = (l & 3) * 2;
#pragma unroll
    for (int nt = 0; nt < 8; nt++) {
        int n = n0 + wr * 16 + rq;
        int cg = h * FOUT + wc * 64 + nt * 8 + cq;
        float2 v0 = {acc[nt][0], acc[nt][1]};
        float2 v1 = {acc[nt][2], acc[nt][3]};
        *(float2*)&out[(size_t)n * COUT + cg] = v0;
        *(float2*)&out[(size_t)(n + 8) * COUT + cg] = v1;
    }
}

// ---------------- launch ----------------
extern "C" void kernel_launch(void* const* d_in, const int* in_sizes, int n_in,
                              void* d_out, int out_size)
{
    const float* x   = (const float*)d_in[0];
    const int*   adj = (const int*)d_in[1];
    const float* W   = (const float*)d_in[2];
    const float* b   = (const float*)d_in[3];
    const float* aw  = (const float*)d_in[4];
    const float* ab  = (const float*)d_in[5];
    float* out = (float*)d_out;

    (void)cudaFuncSetAttribute(k_attn_mma, cudaFuncAttributeMaxDynamicSharedMemorySize, SMEM_TOTAL);

    k_gemm_h<<<dim3(COUT / 64, NN / 64), 256>>>(x, W, b);
    k_scores<<<NN, 128>>>(aw, ab);
    k_stats<<<NN, 256>>>(adj);
    k_cvt<<<dim3(NN / 32, COUT / 32), 256>>>();
    k_attn_mma<<<256, 256, SMEM_TOTAL>>>(adj, out);
}

// round 7
// speedup vs baseline: 2.6469x; 1.2597x over previous
#include <cuda_runtime.h>
#include <cuda_bf16.h>
#include <stdint.h>

#define NN 4096
#define FIN 512
#define FOUT 128
#define HEADS 4
#define COUT 512
#define ALPHA 0.2f

// ---------------- scratch ----------------
__device__ __align__(128) float g_H[NN * COUT];                 // [m][c_global] fp32, 8MB
__device__ __align__(128) float g_src[HEADS * NN];
__device__ __align__(128) float g_dst[HEADS * NN];
__device__ __align__(128) __nv_bfloat16 g_Hthi[COUT * NN];      // [c_global][m] bf16 hi, 4MB
__device__ __align__(128) __nv_bfloat16 g_Htlo[COUT * NN];      // bf16 residual, 4MB

// ---------------- helpers ----------------
__device__ __forceinline__ uint32_t smem_u32(const void* p) {
    uint32_t a;
    asm("{ .reg .u64 t; cvta.to.shared.u64 t, %1; cvt.u32.u64 %0, t; }" : "=r"(a) : "l"(p));
    return a;
}
#define SWZ(off) ((off) ^ (((off) >> 3) & 0x70))
#define CP_ASYNC16(dst, src) \
    asm volatile("cp.async.cg.shared.global [%0], [%1], 16;" :: "r"(dst), "l"(src) : "memory")
#define CP_COMMIT() asm volatile("cp.async.commit_group;" ::: "memory")
#define CP_WAIT0()  asm volatile("cp.async.wait_group 0;" ::: "memory")

__device__ __forceinline__ void ldsm4(uint32_t* r, uint32_t a) {
    asm volatile("ldmatrix.sync.aligned.m8n8.x4.shared.b16 {%0,%1,%2,%3}, [%4];"
                 : "=r"(r[0]), "=r"(r[1]), "=r"(r[2]), "=r"(r[3]) : "r"(a));
}
__device__ __forceinline__ void mma16816(float* d, const uint32_t* a, const uint32_t* b) {
    asm volatile(
        "mma.sync.aligned.m16n8k16.row.col.f32.bf16.bf16.f32 "
        "{%0,%1,%2,%3},{%4,%5,%6,%7},{%8,%9},{%0,%1,%2,%3};"
        : "+f"(d[0]), "+f"(d[1]), "+f"(d[2]), "+f"(d[3])
        : "r"(a[0]), "r"(a[1]), "r"(a[2]), "r"(a[3]), "r"(b[0]), "r"(b[1]));
}

// ---------------- Kernel 1: g_H = x @ Wc + b ----------------
__global__ __launch_bounds__(256) void k_gemm_h(
    const float* __restrict__ x, const float* __restrict__ W, const float* __restrict__ b)
{
    __shared__ float As[16][68];
    __shared__ float Bs[16][68];
    const int t = threadIdx.x;
    const int tx = t & 15, ty = t >> 4;
    const int c0 = blockIdx.x * 64;
    const int n0 = blockIdx.y * 64;
    const int h = c0 >> 7, ob = c0 & 127;
    const float* Wh = W + h * FIN * FOUT;

    float acc[4][4];
#pragma unroll
    for (int i = 0; i < 4; i++)
#pragma unroll
        for (int j = 0; j < 4; j++) acc[i][j] = 0.f;

    const int arow = t >> 2, aks = (t & 3) * 4;
    const int bk = t >> 4, bcs = (t & 15) * 4;

    for (int k0 = 0; k0 < FIN; k0 += 16) {
        float4 av = *(const float4*)&x[(n0 + arow) * FIN + k0 + aks];
        As[aks + 0][arow] = av.x;
        As[aks + 1][arow] = av.y;
        As[aks + 2][arow] = av.z;
        As[aks + 3][arow] = av.w;
        *(float4*)&Bs[bk][bcs] = *(const float4*)&Wh[(k0 + bk) * FOUT + ob + bcs];
        __syncthreads();
#pragma unroll
        for (int kk = 0; kk < 16; kk++) {
            float4 a4 = *(float4*)&As[kk][ty * 4];
            float4 b4 = *(float4*)&Bs[kk][tx * 4];
            float aa[4] = {a4.x, a4.y, a4.z, a4.w};
            float bb[4] = {b4.x, b4.y, b4.z, b4.w};
#pragma unroll
            for (int i = 0; i < 4; i++)
#pragma unroll
                for (int j = 0; j < 4; j++) acc[i][j] = fmaf(aa[i], bb[j], acc[i][j]);
        }
        __syncthreads();
    }
    float4 bias = *(const float4*)&b[c0 + tx * 4];
    float bb[4] = {bias.x, bias.y, bias.z, bias.w};
#pragma unroll
    for (int i = 0; i < 4; i++) {
        float4 v;
        v.x = acc[i][0] + bb[0]; v.y = acc[i][1] + bb[1];
        v.z = acc[i][2] + bb[2]; v.w = acc[i][3] + bb[3];
        *(float4*)&g_H[(n0 + ty * 4 + i) * COUT + c0 + tx * 4] = v;
    }
}

// ---------------- Kernel 2: scores ----------------
__global__ __launch_bounds__(128) void k_scores(
    const float* __restrict__ aw, const float* __restrict__ ab)
{
    const int n = blockIdx.x;
    const int w = threadIdx.x >> 5, l = threadIdx.x & 31;
    const float* hr = g_H + n * COUT + w * FOUT;
    float ss = 0.f, sd = 0.f;
#pragma unroll
    for (int j = 0; j < 4; j++) {
        int o = l + 32 * j;
        float v = hr[o];
        ss = fmaf(v, aw[w * 256 + o], ss);
        sd = fmaf(v, aw[w * 256 + 128 + o], sd);
    }
#pragma unroll
    for (int off = 16; off; off >>= 1) {
        ss += __shfl_xor_sync(0xffffffffu, ss, off);
        sd += __shfl_xor_sync(0xffffffffu, sd, off);
    }
    if (l == 0) {
        g_src[w * NN + n] = ss + ab[w];
        g_dst[w * NN + n] = sd;
    }
}

// ---------------- Kernel 3: transpose + bf16 hi/lo split of H ----------------
__global__ __launch_bounds__(256) void k_cvt()
{
    __shared__ float tile[32][33];
    const int tx = threadIdx.x & 31, ty = threadIdx.x >> 5;
    const int m0 = blockIdx.x * 32, c0 = blockIdx.y * 32;
#pragma unroll
    for (int k = 0; k < 4; k++)
        tile[ty + 8 * k][tx] = g_H[(size_t)(m0 + ty + 8 * k) * COUT + c0 + tx];
    __syncthreads();
#pragma unroll
    for (int k = 0; k < 4; k++) {
        int cg = c0 + ty + 8 * k;
        float v = tile[tx][ty + 8 * k];
        __nv_bfloat16 hi = __float2bfloat16(v);
        __nv_bfloat16 lo = __float2bfloat16(v - __bfloat162float(hi));
        g_Hthi[(size_t)cg * NN + m0 + tx] = hi;
        g_Htlo[(size_t)cg * NN + m0 + tx] = lo;
    }
}

// ---------------- Kernel 4: out = softmax(P) @ H, fused normalization ----------------
// smem: Ah[2]@0 (8KB ea), Al[2]@16K, Bh[2]@32K (16KB ea), Bl[2]@64K, srow@96K ; 96.5KB
#define TILE_PA 8192
#define TILE_HB 16384
#define SM_AH(buf) ((buf) * TILE_PA)
#define SM_AL(buf) (16384 + (buf) * TILE_PA)
#define SM_BH(buf) (32768 + (buf) * TILE_HB)
#define SM_BL(buf) (65536 + (buf) * TILE_HB)
#define SM_SROW 98304
#define SMEM_TOTAL (98304 + 512)

__global__ __launch_bounds__(256, 2) void k_attn_mma(const int* __restrict__ adj, float* __restrict__ out)
{
    extern __shared__ char smem[];
    const uint32_t sb = smem_u32(smem);
    const int t = threadIdx.x;
    const int wid = t >> 5, l = t & 31;
    const int h = blockIdx.x & 3;
    const int n0 = (blockIdx.x >> 2) * 64;

    // ---- staging roles ----
    const int np = t >> 2, mg = (t & 3) * 16;     // P: row np (0..63), m-offset mg
    const int cr = t >> 1, mh = (t & 1) * 32;     // H: row cr (0..127), m-offset mh
    const float sS = g_src[h * NN + n0 + np];
    const int* arow = adj + (size_t)(n0 + np) * NN + mg;
    const float* gdst = g_dst + h * NN + mg;
    const __nv_bfloat16* ghi = g_Hthi + (size_t)(h * 128 + cr) * NN + mh;
    const __nv_bfloat16* glo = g_Htlo + (size_t)(h * 128 + cr) * NN + mh;
    const uint32_t baseB = (uint32_t)(cr * 128 + mh * 2);
    const uint32_t baseA = (uint32_t)(np * 128 + mg * 2);

    // ---- compute role: warp (wr, wc) owns 16n x 64c ----
    const int wr = wid & 3;
    const int wc = wid >> 2;
    const uint32_t aBase = (uint32_t)((wr * 16 + (l & 15)) * 128 + ((l >> 4) << 4));
    uint32_t bBase[4];
#pragma unroll
    for (int gg = 0; gg < 4; gg++)
        bBase[gg] = (uint32_t)((wc * 64 + gg * 16 + (l & 15)) * 128 + ((l >> 4) << 4));

    float acc[8][4];
#pragma unroll
    for (int nt = 0; nt < 8; nt++)
#pragma unroll
        for (int q = 0; q < 4; q++) acc[nt][q] = 0.f;

    float psum = 0.f;   // running row-sum of raw exp (masked)

    // H tiles via cp.async (no register round-trip)
    auto stageH = [&](int chunk) {
        const int m0 = chunk * 64;
        const int buf = chunk & 1;
        const uint32_t bh = sb + SM_BH(buf);
        const uint32_t bl = sb + SM_BL(buf);
#pragma unroll
        for (int q = 0; q < 4; q++) CP_ASYNC16(bh + SWZ(baseB + q * 16), ghi + m0 + q * 8);
#pragma unroll
        for (int q = 0; q < 4; q++) CP_ASYNC16(bl + SWZ(baseB + q * 16), glo + m0 + q * 8);
    };

    // P tile: raw exp (unnormalized), bf16 hi/lo; accumulate psum
    auto stageP = [&](int chunk) {
        const int m0 = chunk * 64;
        const int buf = chunk & 1;
        char* Ah = smem + SM_AH(buf);
        char* Al = smem + SM_AL(buf);
#pragma unroll
        for (int half = 0; half < 2; half++) {
            int4 a0 = *(const int4*)(arow + m0 + half * 8);
            int4 a1 = *(const int4*)(arow + m0 + half * 8 + 4);
            float4 d0 = *(const float4*)(gdst + m0 + half * 8);
            float4 d1 = *(const float4*)(gdst + m0 + half * 8 + 4);
            int av[8] = {a0.x, a0.y, a0.z, a0.w, a1.x, a1.y, a1.z, a1.w};
            float dv[8] = {d0.x, d0.y, d0.z, d0.w, d1.x, d1.y, d1.z, d1.w};
            __align__(16) __nv_bfloat16 hb[8];
            __align__(16) __nv_bfloat16 lb[8];
#pragma unroll
            for (int j = 0; j < 8; j++) {
                float xx = sS + dv[j];
                float e = xx > 0.f ? xx : ALPHA * xx;
                float p = (av[j] > 0) ? __expf(e) : 0.f;
                psum += p;
                __nv_bfloat16 hi = __float2bfloat16(p);
                hb[j] = hi;
                lb[j] = __float2bfloat16(p - __bfloat162float(hi));
            }
            uint32_t sw = SWZ(baseA + half * 16);
            *(uint4*)(Ah + sw) = *(const uint4*)hb;
            *(uint4*)(Al + sw) = *(const uint4*)lb;
        }
    };

    auto compute = [&](int buf) {
        const uint32_t tAh = sb + SM_AH(buf);
        const uint32_t tAl = sb + SM_AL(buf);
        const uint32_t tBh = sb + SM_BH(buf);
        const uint32_t tBl = sb + SM_BL(buf);
#pragma unroll
        for (int ks = 0; ks < 4; ks++) {
            uint32_t ah[4], al[4], bh[4][4], bl[4][4];
            ldsm4(ah, tAh + SWZ(aBase + ks * 32));
            ldsm4(al, tAl + SWZ(aBase + ks * 32));
#pragma unroll
            for (int gg = 0; gg < 4; gg++) {
                ldsm4(bh[gg], tBh + SWZ(bBase[gg] + ks * 32));
                ldsm4(bl[gg], tBl + SWZ(bBase[gg] + ks * 32));
            }
#pragma unroll
            for (int nt = 0; nt < 8; nt++) {
                uint32_t bfh[2] = {bh[nt >> 1][nt & 1], bh[nt >> 1][(nt & 1) + 2]};
                uint32_t bfl[2] = {bl[nt >> 1][nt & 1], bl[nt >> 1][(nt & 1) + 2]};
                mma16816(acc[nt], ah, bfh);
                mma16816(acc[nt], al, bfh);
                mma16816(acc[nt], ah, bfl);
            }
        }
    };

    // prologue
    stageH(0);
    CP_COMMIT();
    stageP(0);
    CP_WAIT0();
    __syncthreads();

    for (int chunk = 0; chunk < 64; chunk++) {
        if (chunk + 1 < 64) {
            stageH(chunk + 1);
            CP_COMMIT();
            stageP(chunk + 1);
        }
        compute(chunk & 1);
        CP_WAIT0();
        __syncthreads();
    }

    // ---- row-sum reduction: 4 threads per row ----
    psum += __shfl_xor_sync(0xffffffffu, psum, 1);
    psum += __shfl_xor_sync(0xffffffffu, psum, 2);
    float* srow = (float*)(smem + SM_SROW);
    if ((t & 3) == 0) srow[np] = psum;
    __syncthreads();

    // ---- epilogue: normalize + store ----
    const int rq = l >> 2, cq = (l & 3) * 2;
    const float inv0 = 1.0f / srow[wr * 16 + rq];
    const float inv1 = 1.0f / srow[wr * 16 + rq + 8];
#pragma unroll
    for (int nt = 0; nt < 8; nt++) {
        int n = n0 + wr * 16 + rq;
        int cg = h * FOUT + wc * 64 + nt * 8 + cq;
        float2 v0 = {acc[nt][0] * inv0, acc[nt][1] * inv0};
        float2 v1 = {acc[nt][2] * inv1, acc[nt][3] * inv1};
        *(float2*)&out[(size_t)n * COUT + cg] = v0;
        *(float2*)&out[(size_t)(n + 8) * COUT + cg] = v1;
    }
}

// ---------------- launch ----------------
extern "C" void kernel_launch(void* const* d_in, const int* in_sizes, int n_in,
                              void* d_out, int out_size)
{
    const float* x   = (const float*)d_in[0];
    const int*   adj = (const int*)d_in[1];
    const float* W   = (const float*)d_in[2];
    const float* b   = (const float*)d_in[3];
    const float* aw  = (const float*)d_in[4];
    const float* ab  = (const float*)d_in[5];
    float* out = (float*)d_out;

    (void)cudaFuncSetAttribute(k_attn_mma, cudaFuncAttributeMaxDynamicSharedMemorySize, SMEM_TOTAL);

    k_gemm_h<<<dim3(COUT / 64, NN / 64), 256>>>(x, W, b);
    k_scores<<<NN, 128>>>(aw, ab);
    k_cvt<<<dim3(NN / 32, COUT / 32), 256>>>();
    k_attn_mma<<<256, 256, SMEM_TOTAL>>>(adj, out);
}

// round 8
// speedup vs baseline: 3.0088x; 1.1367x over previous
#include <cuda_runtime.h>
#include <cuda_bf16.h>
#include <stdint.h>

#define NN 4096
#define FIN 512
#define FOUT 128
#define HEADS 4
#define COUT 512
#define ALPHA 0.2f

// ---------------- scratch ----------------
__device__ __align__(128) float g_H[NN * COUT];                 // [m][c] fp32, 8MB
__device__ __align__(128) float g_src[HEADS * NN];
__device__ __align__(128) float g_dst[HEADS * NN];
__device__ __align__(128) __nv_bfloat16 g_Hthi[COUT * NN];      // [c][m] bf16 hi
__device__ __align__(128) __nv_bfloat16 g_Htlo[COUT * NN];      // bf16 residual
__device__ __align__(128) __nv_bfloat16 g_xhi[NN * FIN];        // [m][i]
__device__ __align__(128) __nv_bfloat16 g_xlo[NN * FIN];
__device__ __align__(128) __nv_bfloat16 g_Wthi[COUT * FIN];     // [c][i]
__device__ __align__(128) __nv_bfloat16 g_Wtlo[COUT * FIN];

// ---------------- helpers ----------------
__device__ __forceinline__ uint32_t smem_u32(const void* p) {
    uint32_t a;
    asm("{ .reg .u64 t; cvta.to.shared.u64 t, %1; cvt.u32.u64 %0, t; }" : "=r"(a) : "l"(p));
    return a;
}
#define SWZ(off) ((off) ^ (((off) >> 3) & 0x70))
#define CP_ASYNC16(dst, src) \
    asm volatile("cp.async.cg.shared.global [%0], [%1], 16;" :: "r"(dst), "l"(src) : "memory")
#define CP_COMMIT() asm volatile("cp.async.commit_group;" ::: "memory")
#define CP_WAIT0()  asm volatile("cp.async.wait_group 0;" ::: "memory")

__device__ __forceinline__ void ldsm4(uint32_t* r, uint32_t a) {
    asm volatile("ldmatrix.sync.aligned.m8n8.x4.shared.b16 {%0,%1,%2,%3}, [%4];"
                 : "=r"(r[0]), "=r"(r[1]), "=r"(r[2]), "=r"(r[3]) : "r"(a));
}
__device__ __forceinline__ void mma16816(float* d, const uint32_t* a, uint32_t b0, uint32_t b1) {
    asm volatile(
        "mma.sync.aligned.m16n8k16.row.col.f32.bf16.bf16.f32 "
        "{%0,%1,%2,%3},{%4,%5,%6,%7},{%8,%9},{%0,%1,%2,%3};"
        : "+f"(d[0]), "+f"(d[1]), "+f"(d[2]), "+f"(d[3])
        : "r"(a[0]), "r"(a[1]), "r"(a[2]), "r"(a[3]), "r"(b0), "r"(b1));
}
__device__ __forceinline__ void split_bf16(float v, __nv_bfloat16& hi, __nv_bfloat16& lo) {
    hi = __float2bfloat16(v);
    lo = __float2bfloat16(v - __bfloat162float(hi));
}

// ---------------- Kernel A: split x into bf16 hi/lo ----------------
__global__ __launch_bounds__(256) void k_split_x(const float* __restrict__ x)
{
    const int base = (blockIdx.x * 256 + threadIdx.x) * 8;
    float4 v0 = *(const float4*)(x + base);
    float4 v1 = *(const float4*)(x + base + 4);
    float v[8] = {v0.x, v0.y, v0.z, v0.w, v1.x, v1.y, v1.z, v1.w};
    __align__(16) __nv_bfloat16 hb[8], lb[8];
#pragma unroll
    for (int j = 0; j < 8; j++) split_bf16(v[j], hb[j], lb[j]);
    *(uint4*)(g_xhi + base) = *(const uint4*)hb;
    *(uint4*)(g_xlo + base) = *(const uint4*)lb;
}

// ---------------- Kernel B: W[h][i][o] -> Wt[c][i] bf16 hi/lo ----------------
__global__ __launch_bounds__(256) void k_split_w(const float* __restrict__ W)
{
    __shared__ float tile[32][33];
    const int tx = threadIdx.x & 31, ty = threadIdx.x >> 5;
    const int i0 = blockIdx.x * 32, o0 = blockIdx.y * 32, h = blockIdx.z;
#pragma unroll
    for (int k = 0; k < 4; k++)
        tile[ty + 8 * k][tx] = W[((size_t)h * FIN + i0 + ty + 8 * k) * FOUT + o0 + tx];
    __syncthreads();
#pragma unroll
    for (int k = 0; k < 4; k++) {
        int o = o0 + ty + 8 * k;
        float v = tile[tx][ty + 8 * k];
        __nv_bfloat16 hi, lo;
        split_bf16(v, hi, lo);
        g_Wthi[(size_t)(h * FOUT + o) * FIN + i0 + tx] = hi;
        g_Wtlo[(size_t)(h * FOUT + o) * FIN + i0 + tx] = lo;
    }
}

// ---------------- Kernel 1: g_H = x @ Wc + b via HMMA ----------------
// CTA: 128m x 64c, K chunks of 64. smem 96KB.
#define GA_H(buf) ((buf) * 16384)
#define GA_L(buf) (32768 + (buf) * 16384)
#define GB_H(buf) (65536 + (buf) * 8192)
#define GB_L(buf) (81920 + (buf) * 8192)
#define GSMEM 98304

__global__ __launch_bounds__(256, 2) void k_gemm_h(const float* __restrict__ b)
{
    extern __shared__ char smem[];
    const uint32_t sb = smem_u32(smem);
    const int t = threadIdx.x;
    const int wid = t >> 5, l = t & 31;
    const int m0 = blockIdx.x * 128;
    const int c0 = blockIdx.y * 64;

    // staging: A thread -> (row 0..127, 64B half); B thread -> (row 0..63, 32B quarter)
    const int ar = t >> 1, ah_ = (t & 1);
    const int br = t >> 2, bq = (t & 3);
    const __nv_bfloat16* xh = g_xhi + (size_t)(m0 + ar) * FIN + ah_ * 32;
    const __nv_bfloat16* xl = g_xlo + (size_t)(m0 + ar) * FIN + ah_ * 32;
    const __nv_bfloat16* wh = g_Wthi + (size_t)(c0 + br) * FIN + bq * 16;
    const __nv_bfloat16* wl = g_Wtlo + (size_t)(c0 + br) * FIN + bq * 16;
    uint32_t aDst[4], bDst[2];
#pragma unroll
    for (int q = 0; q < 4; q++) aDst[q] = SWZ((uint32_t)(ar * 128 + ah_ * 64 + q * 16));
#pragma unroll
    for (int q = 0; q < 2; q++) bDst[q] = SWZ((uint32_t)(br * 128 + bq * 32 + q * 16));

    // compute: warp (wr 0..3, wc 0..1) -> 32m x 32c
    const int wr = wid & 3, wc = wid >> 2;
    uint32_t aOff[4], bOff[2][4];
    {
        uint32_t aBase = (uint32_t)((wr * 32 + (l & 15)) * 128 + ((l >> 4) << 4));
#pragma unroll
        for (int ks = 0; ks < 4; ks++) aOff[ks] = SWZ(aBase + ks * 32);
#pragma unroll
        for (int gg = 0; gg < 2; gg++) {
            uint32_t bBase = (uint32_t)((wc * 32 + gg * 16 + (l & 15)) * 128 + ((l >> 4) << 4));
#pragma unroll
            for (int ks = 0; ks < 4; ks++) bOff[gg][ks] = SWZ(bBase + ks * 32);
        }
    }

    float acc[2][4][4];
#pragma unroll
    for (int mt = 0; mt < 2; mt++)
#pragma unroll
        for (int nt = 0; nt < 4; nt++)
#pragma unroll
            for (int q = 0; q < 4; q++) acc[mt][nt][q] = 0.f;

    auto stage = [&](int chunk) {
        const int k0 = chunk * 64;
        const int buf = chunk & 1;
        const uint32_t pah = sb + GA_H(buf), pal = sb + GA_L(buf);
        const uint32_t pbh = sb + GB_H(buf), pbl = sb + GB_L(buf);
#pragma unroll
        for (int q = 0; q < 4; q++) CP_ASYNC16(pah + aDst[q], xh + k0 + q * 8);
#pragma unroll
        for (int q = 0; q < 4; q++) CP_ASYNC16(pal + aDst[q], xl + k0 + q * 8);
#pragma unroll
        for (int q = 0; q < 2; q++) CP_ASYNC16(pbh + bDst[q], wh + k0 + q * 8);
#pragma unroll
        for (int q = 0; q < 2; q++) CP_ASYNC16(pbl + bDst[q], wl + k0 + q * 8);
    };

    auto compute = [&](int buf) {
        const uint32_t tAh = sb + GA_H(buf), tAl = sb + GA_L(buf);
        const uint32_t tBh = sb + GB_H(buf), tBl = sb + GB_L(buf);
#pragma unroll
        for (int ks = 0; ks < 4; ks++) {
            uint32_t ah0[4], ah1[4], al0[4], al1[4];
            ldsm4(ah0, tAh + aOff[ks]);
            ldsm4(ah1, tAh + aOff[ks] + 2048);
            ldsm4(al0, tAl + aOff[ks]);
            ldsm4(al1, tAl + aOff[ks] + 2048);
#pragma unroll
            for (int gg = 0; gg < 2; gg++) {
                uint32_t bh[4], bl[4];
                ldsm4(bh, tBh + bOff[gg][ks]);
                ldsm4(bl, tBl + bOff[gg][ks]);
#pragma unroll
                for (int j = 0; j < 2; j++) {
                    int nt = gg * 2 + j;
                    mma16816(acc[0][nt], ah0, bh[j], bh[j + 2]);
                    mma16816(acc[0][nt], al0, bh[j], bh[j + 2]);
                    mma16816(acc[0][nt], ah0, bl[j], bl[j + 2]);
                    mma16816(acc[1][nt], ah1, bh[j], bh[j + 2]);
                    mma16816(acc[1][nt], al1, bh[j], bh[j + 2]);
                    mma16816(acc[1][nt], ah1, bl[j], bl[j + 2]);
                }
            }
        }
    };

    stage(0);
    CP_COMMIT();
    CP_WAIT0();
    __syncthreads();
    for (int chunk = 0; chunk < 8; chunk++) {
        if (chunk + 1 < 8) { stage(chunk + 1); CP_COMMIT(); }
        compute(chunk & 1);
        CP_WAIT0();
        __syncthreads();
    }

    const int rq = l >> 2, cq = (l & 3) * 2;
#pragma unroll
    for (int nt = 0; nt < 4; nt++) {
        int cg = c0 + wc * 32 + nt * 8 + cq;
        float2 bias = *(const float2*)&b[cg];
#pragma unroll
        for (int mt = 0; mt < 2; mt++) {
            int m = m0 + wr * 32 + mt * 16 + rq;
            float2 v0 = {acc[mt][nt][0] + bias.x, acc[mt][nt][1] + bias.y};
            float2 v1 = {acc[mt][nt][2] + bias.x, acc[mt][nt][3] + bias.y};
            *(float2*)&g_H[(size_t)m * COUT + cg] = v0;
            *(float2*)&g_H[(size_t)(m + 8) * COUT + cg] = v1;
        }
    }
}

// ---------------- Kernel 2: scores ----------------
__global__ __launch_bounds__(128) void k_scores(
    const float* __restrict__ aw, const float* __restrict__ ab)
{
    const int n = blockIdx.x;
    const int w = threadIdx.x >> 5, l = threadIdx.x & 31;
    const float* hr = g_H + n * COUT + w * FOUT;
    float ss = 0.f, sd = 0.f;
#pragma unroll
    for (int j = 0; j < 4; j++) {
        int o = l + 32 * j;
        float v = hr[o];
        ss = fmaf(v, aw[w * 256 + o], ss);
        sd = fmaf(v, aw[w * 256 + 128 + o], sd);
    }
#pragma unroll
    for (int off = 16; off; off >>= 1) {
        ss += __shfl_xor_sync(0xffffffffu, ss, off);
        sd += __shfl_xor_sync(0xffffffffu, sd, off);
    }
    if (l == 0) {
        g_src[w * NN + n] = ss + ab[w];
        g_dst[w * NN + n] = sd;
    }
}

// ---------------- Kernel 3: transpose + bf16 hi/lo split of H ----------------
__global__ __launch_bounds__(256) void k_cvt()
{
    __shared__ float tile[32][33];
    const int tx = threadIdx.x & 31, ty = threadIdx.x >> 5;
    const int m0 = blockIdx.x * 32, c0 = blockIdx.y * 32;
#pragma unroll
    for (int k = 0; k < 4; k++)
        tile[ty + 8 * k][tx] = g_H[(size_t)(m0 + ty + 8 * k) * COUT + c0 + tx];
    __syncthreads();
#pragma unroll
    for (int k = 0; k < 4; k++) {
        int cg = c0 + ty + 8 * k;
        float v = tile[tx][ty + 8 * k];
        __nv_bfloat16 hi, lo;
        split_bf16(v, hi, lo);
        g_Hthi[(size_t)cg * NN + m0 + tx] = hi;
        g_Htlo[(size_t)cg * NN + m0 + tx] = lo;
    }
}

// ---------------- Kernel 4: out = softmax(P) @ H, fused normalization ----------------
#define TILE_PA 8192
#define TILE_HB 16384
#define SM_AH(buf) ((buf) * TILE_PA)
#define SM_AL(buf) (16384 + (buf) * TILE_PA)
#define SM_BH(buf) (32768 + (buf) * TILE_HB)
#define SM_BL(buf) (65536 + (buf) * TILE_HB)
#define SM_SROW 98304
#define SMEM_TOTAL (98304 + 512)

__global__ __launch_bounds__(256, 2) void k_attn_mma(const int* __restrict__ adj, float* __restrict__ out)
{
    extern __shared__ char smem[];
    const uint32_t sb = smem_u32(smem);
    const int t = threadIdx.x;
    const int wid = t >> 5, l = t & 31;
    const int h = blockIdx.x & 3;
    const int n0 = (blockIdx.x >> 2) * 64;

    // ---- staging roles ----
    const int np = t >> 2, mg = (t & 3) * 16;     // P: row np (0..63), m-offset mg
    const int cr = t >> 1, mh = (t & 1) * 32;     // H: row cr (0..127), m-offset mh
    const float sS = g_src[h * NN + n0 + np];
    const int* arow = adj + (size_t)(n0 + np) * NN + mg;
    const float* gdst = g_dst + h * NN + mg;
    const __nv_bfloat16* ghi = g_Hthi + (size_t)(h * 128 + cr) * NN + mh;
    const __nv_bfloat16* glo = g_Htlo + (size_t)(h * 128 + cr) * NN + mh;
    uint32_t hDst[4], pDst[2];
    {
        uint32_t baseB = (uint32_t)(cr * 128 + mh * 2);
        uint32_t baseA = (uint32_t)(np * 128 + mg * 2);
#pragma unroll
        for (int q = 0; q < 4; q++) hDst[q] = SWZ(baseB + q * 16);
#pragma unroll
        for (int q = 0; q < 2; q++) pDst[q] = SWZ(baseA + q * 16);
    }

    // ---- compute role: warp (wr, wc) owns 16n x 64c; precomputed swizzled offsets ----
    const int wr = wid & 3;
    const int wc = wid >> 2;
    uint32_t aOff[4], bOff[4][4];
    {
        uint32_t aBase = (uint32_t)((wr * 16 + (l & 15)) * 128 + ((l >> 4) << 4));
#pragma unroll
        for (int ks = 0; ks < 4; ks++) aOff[ks] = SWZ(aBase + ks * 32);
#pragma unroll
        for (int gg = 0; gg < 4; gg++) {
            uint32_t bBase = (uint32_t)((wc * 64 + gg * 16 + (l & 15)) * 128 + ((l >> 4) << 4));
#pragma unroll
            for (int ks = 0; ks < 4; ks++) bOff[gg][ks] = SWZ(bBase + ks * 32);
        }
    }

    float acc[8][4];
#pragma unroll
    for (int nt = 0; nt < 8; nt++)
#pragma unroll
        for (int q = 0; q < 4; q++) acc[nt][q] = 0.f;

    float psum = 0.f;

    auto stageH = [&](int chunk) {
        const int m0 = chunk * 64;
        const int buf = chunk & 1;
        const uint32_t bh = sb + SM_BH(buf);
        const uint32_t bl = sb + SM_BL(buf);
#pragma unroll
        for (int q = 0; q < 4; q++) CP_ASYNC16(bh + hDst[q], ghi + m0 + q * 8);
#pragma unroll
        for (int q = 0; q < 4; q++) CP_ASYNC16(bl + hDst[q], glo + m0 + q * 8);
    };

    auto stageP = [&](int chunk) {
        const int m0 = chunk * 64;
        const int buf = chunk & 1;
        char* Ah = smem + SM_AH(buf);
        char* Al = smem + SM_AL(buf);
#pragma unroll
        for (int half = 0; half < 2; half++) {
            int4 a0 = *(const int4*)(arow + m0 + half * 8);
            int4 a1 = *(const int4*)(arow + m0 + half * 8 + 4);
            float4 d0 = *(const float4*)(gdst + m0 + half * 8);
            float4 d1 = *(const float4*)(gdst + m0 + half * 8 + 4);
            int av[8] = {a0.x, a0.y, a0.z, a0.w, a1.x, a1.y, a1.z, a1.w};
            float dv[8] = {d0.x, d0.y, d0.z, d0.w, d1.x, d1.y, d1.z, d1.w};
            __align__(16) __nv_bfloat16 hb[8];
            __align__(16) __nv_bfloat16 lb[8];
#pragma unroll
            for (int j = 0; j < 8; j++) {
                float xx = sS + dv[j];
                float e = xx > 0.f ? xx : ALPHA * xx;
                float p = (av[j] > 0) ? __expf(e) : 0.f;
                psum += p;
                split_bf16(p, hb[j], lb[j]);
            }
            *(uint4*)(Ah + pDst[half]) = *(const uint4*)hb;
            *(uint4*)(Al + pDst[half]) = *(const uint4*)lb;
        }
    };

    auto compute = [&](int buf) {
        const uint32_t tAh = sb + SM_AH(buf);
        const uint32_t tAl = sb + SM_AL(buf);
        const uint32_t tBh = sb + SM_BH(buf);
        const uint32_t tBl = sb + SM_BL(buf);
#pragma unroll
        for (int ks = 0; ks < 4; ks++) {
            uint32_t ah[4], al[4];
            ldsm4(ah, tAh + aOff[ks]);
            ldsm4(al, tAl + aOff[ks]);
#pragma unroll
            for (int gg = 0; gg < 4; gg++) {
                uint32_t bh[4], bl[4];
                ldsm4(bh, tBh + bOff[gg][ks]);
                ldsm4(bl, tBl + bOff[gg][ks]);
#pragma unroll
                for (int j = 0; j < 2; j++) {
                    int nt = gg * 2 + j;
                    mma16816(acc[nt], ah, bh[j], bh[j + 2]);
                    mma16816(acc[nt], al, bh[j], bh[j + 2]);
                    mma16816(acc[nt], ah, bl[j], bl[j + 2]);
                }
            }
        }
    };

    // prologue
    stageH(0);
    CP_COMMIT();
    stageP(0);
    CP_WAIT0();
    __syncthreads();

    for (int chunk = 0; chunk < 64; chunk++) {
        if (chunk + 1 < 64) {
            stageH(chunk + 1);
            CP_COMMIT();
            stageP(chunk + 1);
        }
        compute(chunk & 1);
        CP_WAIT0();
        __syncthreads();
    }

    // ---- row-sum reduction: 4 threads per row ----
    psum += __shfl_xor_sync(0xffffffffu, psum, 1);
    psum += __shfl_xor_sync(0xffffffffu, psum, 2);
    float* srow = (float*)(smem + SM_SROW);
    if ((t & 3) == 0) srow[np] = psum;
    __syncthreads();

    // ---- epilogue: normalize + store ----
    const int rq = l >> 2, cq = (l & 3) * 2;
    const float inv0 = 1.0f / srow[wr * 16 + rq];
    const float inv1 = 1.0f / srow[wr * 16 + rq + 8];
#pragma unroll
    for (int nt = 0; nt < 8; nt++) {
        int n = n0 + wr * 16 + rq;
        int cg = h * FOUT + wc * 64 + nt * 8 + cq;
        float2 v0 = {acc[nt][0] * inv0, acc[nt][1] * inv0};
        float2 v1 = {acc[nt][2] * inv1, acc[nt][3] * inv1};
        *(float2*)&out[(size_t)n * COUT + cg] = v0;
        *(float2*)&out[(size_t)(n + 8) * COUT + cg] = v1;
    }
}

// ---------------- launch ----------------
extern "C" void kernel_launch(void* const* d_in, const int* in_sizes, int n_in,
                              void* d_out, int out_size)
{
    const float* x   = (const float*)d_in[0];
    const int*   adj = (const int*)d_in[1];
    const float* W   = (const float*)d_in[2];
    const float* b   = (const float*)d_in[3];
    const float* aw  = (const float*)d_in[4];
    const float* ab  = (const float*)d_in[5];
    float* out = (float*)d_out;

    (void)cudaFuncSetAttribute(k_gemm_h, cudaFuncAttributeMaxDynamicSharedMemorySize, GSMEM);
    (void)cudaFuncSetAttribute(k_attn_mma, cudaFuncAttributeMaxDynamicSharedMemorySize, SMEM_TOTAL);

    k_split_x<<<NN * FIN / (256 * 8), 256>>>(x);
    k_split_w<<<dim3(FIN / 32, FOUT / 32, HEADS), 256>>>(W);
    k_gemm_h<<<dim3(NN / 128, COUT / 64), 256, GSMEM>>>(b);
    k_scores<<<NN, 128>>>(aw, ab);
    k_cvt<<<dim3(NN / 32, COUT / 32), 256>>>();
    k_attn_mma<<<256, 256, SMEM_TOTAL>>>(adj, out);
}